// round 13
// baseline (speedup 1.0000x reference)
#include <cuda_runtime.h>
#include <cstdint>

#define NPTS  5760
#define BATCH 4
#define CT    384            // columns per tile
#define NCT   15             // 5760 / 384
#define RT    240            // rows per block (R11 geometry restored)
#define NRT   24             // 5760 / 240
#define WARPS 8
#define TPB   256
#define RPW   30             // rows per warp (240 / 8)
#define EPL   12             // elements per lane (384 / 32)
#define GRP   3              // float4 groups per lane
#define LBLK  8              // loss blocks per batch
#define TEMPF 100.0f
#define NEGV  -1e30f
#define TH_OFF 0.30f         // exp cutoff: e^(-30) ~ 1e-13 relative

// -------- scratch (static device globals; no allocation allowed) --------
__device__ float g_rowpart[BATCH * NCT * NPTS * 8];   // per (b,tile,row): m,s,px,py,pz,argcol
__device__ float g_colV[BATCH * NRT * NPTS];          // per (b,rowtile,col): col max value
__device__ float g_colVf[BATCH * NPTS];               // merged col max value
__device__ float g_p2[BATCH * NPTS * 4];              // points2 xyz + row max M
__device__ int   g_i21[BATCH * NPTS];                 // ind2to1
__device__ float4 g_part[BATCH * LBLK];               // loss partials (sm, sd, cnt)
__device__ unsigned g_ctr;                            // ticket counter (self-resetting)

// -------- warp collectives --------
__device__ __forceinline__ unsigned f2ord(float f) {
    unsigned u = __float_as_uint(f);
    return (u & 0x80000000u) ? ~u : (u | 0x80000000u);
}
__device__ __forceinline__ float ord2f(unsigned u) {
    unsigned v = (u & 0x80000000u) ? (u & 0x7fffffffu) : ~u;
    return __uint_as_float(v);
}
__device__ __forceinline__ unsigned warp_max_u32(unsigned v) {
    unsigned r;
    asm volatile("redux.sync.max.u32 %0, %1, 0xffffffff;" : "=r"(r) : "r"(v));
    return r;
}
__device__ __forceinline__ unsigned warp_min_u32(unsigned v) {
    unsigned r;
    asm volatile("redux.sync.min.u32 %0, %1, 0xffffffff;" : "=r"(r) : "r"(v));
    return r;
}

// ================= K1: streaming pass, direct LDG, 2 rows per iteration =====
__global__ void __launch_bounds__(TPB, 4) k_main(const float* __restrict__ match,
                                                 const float* __restrict__ tgt,
                                                 const int*   __restrict__ pmask)
{
    const int b    = blockIdx.z;
    const int tile = blockIdx.x;
    const int rt   = blockIdx.y;
    const int warp = threadIdx.x >> 5;
    const int lane = threadIdx.x & 31;
    const int col0 = tile * CT;
    const int row0 = rt * RT;

    const int* m1p = pmask + (size_t)(2 * b) * NPTS;
    const int* m2p = pmask + (size_t)(2 * b + 1) * NPTS;

    // m2 validity as a 12-bit per-lane mask; column max values in registers
    unsigned m2b = 0;
    float cbv[EPL];
#pragma unroll
    for (int k = 0; k < GRP; k++) {
        int4 mm = *(const int4*)(m2p + col0 + k * 128 + lane * 4);
        m2b |= (mm.x ? 1u : 0u) << (4*k+0);
        m2b |= (mm.y ? 1u : 0u) << (4*k+1);
        m2b |= (mm.z ? 1u : 0u) << (4*k+2);
        m2b |= (mm.w ? 1u : 0u) << (4*k+3);
    }
#pragma unroll
    for (int e = 0; e < EPL; e++) cbv[e] = -INFINITY;

    const float* tgx = tgt + (size_t)(b * 3 + 0) * NPTS;
    const float* tgy = tgt + (size_t)(b * 3 + 1) * NPTS;
    const float* tgz = tgt + (size_t)(b * 3 + 2) * NPTS;

    const int rbeg = row0 + warp * RPW;
    bool vb = (lane < RPW) ? (m1p[rbeg + lane] != 0) : false;
    const unsigned mbits = __ballot_sync(0xffffffffu, vb);
    const int nval = __popc(mbits);

    // per-lane element base within a row (floats)
    const float* mbase = match + ((size_t)b * NPTS) * NPTS + col0 + lane * 4;

    unsigned ccur = mbits;   // consume cursor (bit-scan; uniform across lanes)

    const int npair = (nval + 1) >> 1;
    for (int t = 0; t < npair; t++) {
        const bool hasB = (2 * t + 1 < nval);
        int p0 = __ffs(ccur) - 1; ccur &= ccur - 1;
        int p1 = p0;
        if (hasB) { p1 = __ffs(ccur) - 1; ccur &= ccur - 1; }
        const int rA = rbeg + p0;
        const int rB = rbeg + p1;
        const float* rpA = mbase + (size_t)rA * NPTS;
        const float* rpB = mbase + (size_t)rB * NPTS;

        // ---- issue all 6 loads up front (MLP=6), values live in registers ----
        float4 a0 = *(const float4*)(rpA);
        float4 a1 = *(const float4*)(rpA + 128);
        float4 a2 = *(const float4*)(rpA + 256);
        float4 b0 = *(const float4*)(rpB);
        float4 b1 = *(const float4*)(rpB + 128);
        float4 b2 = *(const float4*)(rpB + 256);

        // ---- sweep: column max + masked group maxes (predicated) ----
        float gmA0, gmA1, gmA2, gmB0, gmB1, gmB2;
        {
            cbv[0]  = fmaxf(cbv[0],  fmaxf(a0.x, b0.x));
            cbv[1]  = fmaxf(cbv[1],  fmaxf(a0.y, b0.y));
            cbv[2]  = fmaxf(cbv[2],  fmaxf(a0.z, b0.z));
            cbv[3]  = fmaxf(cbv[3],  fmaxf(a0.w, b0.w));
            float ga = -INFINITY, gb = -INFINITY;
            if (m2b & (1u << 0)) { ga = fmaxf(ga, a0.x); gb = fmaxf(gb, b0.x); }
            if (m2b & (1u << 1)) { ga = fmaxf(ga, a0.y); gb = fmaxf(gb, b0.y); }
            if (m2b & (1u << 2)) { ga = fmaxf(ga, a0.z); gb = fmaxf(gb, b0.z); }
            if (m2b & (1u << 3)) { ga = fmaxf(ga, a0.w); gb = fmaxf(gb, b0.w); }
            gmA0 = ga; gmB0 = gb;
        }
        {
            cbv[4]  = fmaxf(cbv[4],  fmaxf(a1.x, b1.x));
            cbv[5]  = fmaxf(cbv[5],  fmaxf(a1.y, b1.y));
            cbv[6]  = fmaxf(cbv[6],  fmaxf(a1.z, b1.z));
            cbv[7]  = fmaxf(cbv[7],  fmaxf(a1.w, b1.w));
            float ga = -INFINITY, gb = -INFINITY;
            if (m2b & (1u << 4)) { ga = fmaxf(ga, a1.x); gb = fmaxf(gb, b1.x); }
            if (m2b & (1u << 5)) { ga = fmaxf(ga, a1.y); gb = fmaxf(gb, b1.y); }
            if (m2b & (1u << 6)) { ga = fmaxf(ga, a1.z); gb = fmaxf(gb, b1.z); }
            if (m2b & (1u << 7)) { ga = fmaxf(ga, a1.w); gb = fmaxf(gb, b1.w); }
            gmA1 = ga; gmB1 = gb;
        }
        {
            cbv[8]  = fmaxf(cbv[8],  fmaxf(a2.x, b2.x));
            cbv[9]  = fmaxf(cbv[9],  fmaxf(a2.y, b2.y));
            cbv[10] = fmaxf(cbv[10], fmaxf(a2.z, b2.z));
            cbv[11] = fmaxf(cbv[11], fmaxf(a2.w, b2.w));
            float ga = -INFINITY, gb = -INFINITY;
            if (m2b & (1u << 8))  { ga = fmaxf(ga, a2.x); gb = fmaxf(gb, b2.x); }
            if (m2b & (1u << 9))  { ga = fmaxf(ga, a2.y); gb = fmaxf(gb, b2.y); }
            if (m2b & (1u << 10)) { ga = fmaxf(ga, a2.z); gb = fmaxf(gb, b2.z); }
            if (m2b & (1u << 11)) { ga = fmaxf(ga, a2.w); gb = fmaxf(gb, b2.w); }
            gmA2 = ga; gmB2 = gb;
        }
        const float lmA = fmaxf(fmaxf(gmA0, gmA1), gmA2);
        const float lmB = fmaxf(fmaxf(gmB0, gmB1), gmB2);
        const float wmA = ord2f(warp_max_u32(f2ord(lmA)));
        const float wmB = ord2f(warp_max_u32(f2ord(lmB)));
        const float thA = wmA - TH_OFF;
        const float thB = wmB - TH_OFF;

        // ---- exp phases: lane-local gating, values already in registers ----
        float sA = 0.f, pxA = 0.f, pyA = 0.f, pzA = 0.f;
        float sB = 0.f, pxB = 0.f, pyB = 0.f, pzB = 0.f;
        unsigned bcA = 0x7fffffffu, bcB = 0x7fffffffu;
        if (lmA > thA) {
#pragma unroll
            for (int k = 0; k < GRP; k++) {
                const float gmk = (k == 0) ? gmA0 : (k == 1) ? gmA1 : gmA2;
                if (gmk > thA) {
                    const float4 t4 = (k == 0) ? a0 : (k == 1) ? a1 : a2;
                    const float vv[4] = { t4.x, t4.y, t4.z, t4.w };
#pragma unroll
                    for (int j = 0; j < 4; j++) {
                        float vmv = (m2b & (1u << (4*k + j))) ? vv[j] : NEGV;
                        if (vmv > thA) {
                            float w = __expf((vmv - wmA) * TEMPF);
                            int c = col0 + k * 128 + lane * 4 + j;
                            sA  += w;
                            pxA += w * tgx[c];
                            pyA += w * tgy[c];
                            pzA += w * tgz[c];
                            if (vmv == wmA) bcA = min(bcA, (unsigned)c);
                        }
                    }
                }
            }
        }
        if (lmB > thB) {
#pragma unroll
            for (int k = 0; k < GRP; k++) {
                const float gmk = (k == 0) ? gmB0 : (k == 1) ? gmB1 : gmB2;
                if (gmk > thB) {
                    const float4 t4 = (k == 0) ? b0 : (k == 1) ? b1 : b2;
                    const float vv[4] = { t4.x, t4.y, t4.z, t4.w };
#pragma unroll
                    for (int j = 0; j < 4; j++) {
                        float vmv = (m2b & (1u << (4*k + j))) ? vv[j] : NEGV;
                        if (vmv > thB) {
                            float w = __expf((vmv - wmB) * TEMPF);
                            int c = col0 + k * 128 + lane * 4 + j;
                            sB  += w;
                            pxB += w * tgx[c];
                            pyB += w * tgy[c];
                            pzB += w * tgz[c];
                            if (vmv == wmB) bcB = min(bcB, (unsigned)c);
                        }
                    }
                }
            }
        }

        // ---- reduce & write row A (fast path: single lane writes directly)
        {
            const unsigned bal = __ballot_sync(0xffffffffu, lmA > thA);
            float* out = g_rowpart + ((size_t)(b * NCT + tile) * NPTS + rA) * 8;
            if (__popc(bal) == 1) {
                if (lane == __ffs(bal) - 1) {
                    *(float4*)(out)     = make_float4(wmA, sA, pxA, pyA);
                    *(float4*)(out + 4) = make_float4(pzA, __int_as_float((int)bcA), 0.f, 0.f);
                }
            } else {
#pragma unroll
                for (int o = 16; o; o >>= 1) {
                    sA  += __shfl_xor_sync(0xffffffffu, sA,  o);
                    pxA += __shfl_xor_sync(0xffffffffu, pxA, o);
                    pyA += __shfl_xor_sync(0xffffffffu, pyA, o);
                    pzA += __shfl_xor_sync(0xffffffffu, pzA, o);
                }
                bcA = warp_min_u32(bcA);
                if (lane == 0) {
                    *(float4*)(out)     = make_float4(wmA, sA, pxA, pyA);
                    *(float4*)(out + 4) = make_float4(pzA, __int_as_float((int)bcA), 0.f, 0.f);
                }
            }
        }
        // ---- reduce & write row B (dup-safe) ----
        {
            const unsigned bal = __ballot_sync(0xffffffffu, lmB > thB);
            float* out = g_rowpart + ((size_t)(b * NCT + tile) * NPTS + rB) * 8;
            if (__popc(bal) == 1) {
                if (lane == __ffs(bal) - 1) {
                    *(float4*)(out)     = make_float4(wmB, sB, pxB, pyB);
                    *(float4*)(out + 4) = make_float4(pzB, __int_as_float((int)bcB), 0.f, 0.f);
                }
            } else {
#pragma unroll
                for (int o = 16; o; o >>= 1) {
                    sB  += __shfl_xor_sync(0xffffffffu, sB,  o);
                    pxB += __shfl_xor_sync(0xffffffffu, pxB, o);
                    pyB += __shfl_xor_sync(0xffffffffu, pyB, o);
                    pzB += __shfl_xor_sync(0xffffffffu, pzB, o);
                }
                bcB = warp_min_u32(bcB);
                if (lane == 0) {
                    *(float4*)(out)     = make_float4(wmB, sB, pxB, pyB);
                    *(float4*)(out + 4) = make_float4(pzB, __int_as_float((int)bcB), 0.f, 0.f);
                }
            }
        }
    }
    __syncthreads();

    // block-level column-max merge (values only), static smem (12 KB)
    __shared__ float sv[WARPS][CT];
#pragma unroll
    for (int e = 0; e < EPL; e++) {
        int cl = (e >> 2) * 128 + lane * 4 + (e & 3);
        sv[warp][cl] = cbv[e];
    }
    __syncthreads();
    for (int c = threadIdx.x; c < CT; c += TPB) {
        float bv = -INFINITY;
#pragma unroll
        for (int w = 0; w < WARPS; w++) bv = fmaxf(bv, sv[w][c]);
        g_colV[(size_t)(b * NRT + rt) * NPTS + col0 + c] = bv;
    }
}

// ================= K2: merge row tiles + column tiles (fully parallel) ======
__global__ void __launch_bounds__(256) k_merge(const int* __restrict__ pmask)
{
    const int gid = blockIdx.x * 256 + threadIdx.x;
    const int total = BATCH * NPTS;
    if (gid < total) {
        const int b = gid / NPTS, r = gid - b * NPTS;
        if (!pmask[(size_t)(2 * b) * NPTS + r]) return;
        float M = -INFINITY; int argc = 0;
        float4 A[NCT], Bv[NCT];
#pragma unroll
        for (int t = 0; t < NCT; t++) {
            const float* base = g_rowpart + ((size_t)(b * NCT + t) * NPTS + r) * 8;
            A[t]  = *(const float4*)(base);
            Bv[t] = *(const float4*)(base + 4);
        }
#pragma unroll
        for (int t = 0; t < NCT; t++)
            if (A[t].x > M) { M = A[t].x; argc = __float_as_int(Bv[t].y); }
        float S = 0.f, Px = 0.f, Py = 0.f, Pz = 0.f;
#pragma unroll
        for (int t = 0; t < NCT; t++) {
            float w = __expf((A[t].x - M) * TEMPF);
            S  += A[t].y * w;
            Px += A[t].z * w;
            Py += A[t].w * w;
            Pz += Bv[t].x * w;
        }
        float inv = 1.f / S;
        *(float4*)(g_p2 + (size_t)gid * 4) = make_float4(Px * inv, Py * inv, Pz * inv, M);
        g_i21[gid] = argc;
    } else if (gid < 2 * total) {
        const int g2 = gid - total;
        const int b = g2 / NPTS, c = g2 - b * NPTS;
        float bv = -INFINITY;
#pragma unroll
        for (int t = 0; t < NRT; t++)
            bv = fmaxf(bv, g_colV[(size_t)(b * NRT + t) * NPTS + c]);
        g_colVf[g2] = bv;
    }
}

// ================= K3: parallel loss partials + tiny ticket finish ==========
__global__ void __launch_bounds__(256) k_loss(const float* __restrict__ src,
                                              const float* __restrict__ wts,
                                              const float* __restrict__ Tiv,
                                              const int*   __restrict__ pmask,
                                              float* __restrict__ out)
{
    const int b   = blockIdx.x / LBLK;
    const int blk = blockIdx.x % LBLK;
    const int CH  = NPTS / LBLK;                 // 720 points per block

    __shared__ float T21[12];
    if (threadIdx.x == 0) {
        const float* Ts = Tiv + (size_t)(2 * b) * 16;
        const float* Tt = Tiv + (size_t)(2 * b + 1) * 16;
        float A[3][4];
        for (int i = 0; i < 3; i++) {
            for (int k = 0; k < 3; k++) A[i][k] = Tt[k * 4 + i];
            A[i][3] = -(Tt[0*4+i]*Tt[3] + Tt[1*4+i]*Tt[7] + Tt[2*4+i]*Tt[11]);
        }
        for (int i = 0; i < 3; i++)
            for (int j = 0; j < 4; j++)
                T21[i*4+j] = A[i][0]*Ts[j] + A[i][1]*Ts[4+j]
                           + A[i][2]*Ts[8+j] + A[i][3]*Ts[12+j];
    }
    __syncthreads();

    const float* sx = src + (size_t)(b * 3 + 0) * NPTS;
    const float* sy = src + (size_t)(b * 3 + 1) * NPTS;
    const float* sz = src + (size_t)(b * 3 + 2) * NPTS;
    const float* w0 = wts + (size_t)(b * 6 + 0) * NPTS;
    const float* w1 = wts + (size_t)(b * 6 + 1) * NPTS;
    const float* w2 = wts + (size_t)(b * 6 + 2) * NPTS;
    const float* w3 = wts + (size_t)(b * 6 + 3) * NPTS;
    const float* w4 = wts + (size_t)(b * 6 + 4) * NPTS;
    const float* w5 = wts + (size_t)(b * 6 + 5) * NPTS;
    const int*   m1  = pmask + (size_t)(2 * b) * NPTS;
    const int*   i21 = g_i21 + b * NPTS;
    const float* cvf = g_colVf + b * NPTS;

    float sm = 0.f, sd = 0.f, cnt = 0.f;
    const int i0 = blk * CH;
    for (int i = i0 + threadIdx.x; i < i0 + CH; i += 256) {
        if (!m1[i]) continue;
        float4 pp = *(const float4*)(g_p2 + (size_t)(b * NPTS + i) * 4);
        int j = i21[i];
        if (pp.w != cvf[j]) continue;   // consist: row max == its column's max
        float p0 = sx[i], p1 = sy[i], p2v = sz[i];
        float q0 = T21[0]*p0 + T21[1]*p1 + T21[2] *p2v + T21[3];
        float q1 = T21[4]*p0 + T21[5]*p1 + T21[6] *p2v + T21[7];
        float q2 = T21[8]*p0 + T21[9]*p1 + T21[10]*p2v + T21[11];
        float e0 = q0 - pp.x, e1 = q1 - pp.y, e2 = q2 - pp.z;
        float aa = w0[i], bb = w1[i], cc = w2[i];
        float d0 = w3[i], d1 = w4[i], d2 = w5[i];
        float u0 = e0 + aa * e1 + bb * e2;
        float u1 = e1 + cc * e2;
        float u2 = e2;
        float mah = __expf(d0)*u0*u0 + __expf(d1)*u1*u1 + __expf(d2)*u2*u2;
        if (mah < 10000.0f) { sm += mah; sd += d0 + d1 + d2; cnt += 1.f; }
    }
#pragma unroll
    for (int o = 16; o; o >>= 1) {
        sm  += __shfl_xor_sync(0xffffffffu, sm,  o);
        sd  += __shfl_xor_sync(0xffffffffu, sd,  o);
        cnt += __shfl_xor_sync(0xffffffffu, cnt, o);
    }
    __shared__ float rs[8], rd[8], rc[8];
    if ((threadIdx.x & 31) == 0) {
        rs[threadIdx.x >> 5] = sm;
        rd[threadIdx.x >> 5] = sd;
        rc[threadIdx.x >> 5] = cnt;
    }
    __syncthreads();
    if (threadIdx.x == 0) {
        float S = 0.f, D = 0.f, C = 0.f;
        for (int w = 0; w < 8; w++) { S += rs[w]; D += rd[w]; C += rc[w]; }
        g_part[b * LBLK + blk] = make_float4(S, D, C, 0.f);
    }

    // ticket: last block finishes (tiny deterministic sum over 32 partials)
    __threadfence();
    __syncthreads();
    __shared__ unsigned amlast;
    if (threadIdx.x == 0)
        amlast = (atomicAdd(&g_ctr, 1u) == gridDim.x - 1);
    __syncthreads();
    if (!amlast) return;
    __threadfence();

    if (threadIdx.x == 0) {
        float acc = 0.f;
        for (int bb = 0; bb < BATCH; bb++) {
            float S = 0.f, D = 0.f, C = 0.f;
            for (int k = 0; k < LBLK; k++) {
                float4 p = g_part[bb * LBLK + k];
                S += p.x; D += p.y; C += p.z;
            }
            acc += (S - D) / fmaxf(C, 1.f);
        }
        out[0] = acc;
        g_ctr = 0;
    }
}

// ================= launch ====================================================
extern "C" void kernel_launch(void* const* d_in, const int* in_sizes, int n_in,
                              void* d_out, int out_size)
{
    const float* src   = (const float*)d_in[0];   // (4,3,5760)
    const float* tgt   = (const float*)d_in[1];   // (4,3,5760)
    const float* wts   = (const float*)d_in[2];   // (4,6,5760)
    const float* match = (const float*)d_in[3];   // (4,5760,5760)
    const float* Tiv   = (const float*)d_in[4];   // (8,4,4)
    const int*   pmask = (const int*)d_in[5];     // (8,5760)

    dim3 g1(NCT, NRT, BATCH);                     // 15 x 24 x 4 = 1440 blocks
    k_main<<<g1, TPB>>>(match, tgt, pmask);

    const int total2 = 2 * BATCH * NPTS;
    k_merge<<<(total2 + 255) / 256, 256>>>(pmask);
    k_loss<<<BATCH * LBLK, 256>>>(src, wts, Tiv, pmask, (float*)d_out);
}

// round 14
// speedup vs baseline: 1.3960x; 1.3960x over previous
#include <cuda_runtime.h>
#include <cstdint>

#define NPTS  5760
#define BATCH 4
#define CT    384            // columns per tile
#define NCT   15             // 5760 / 384
#define RT    240            // rows per block
#define NRT   24             // 5760 / 240
#define WARPS 8
#define TPB   256
#define RPW   30             // rows per warp (240 / 8)
#define EPL   12             // elements per lane (384 / 32)
#define GRP   3              // float4 groups per lane
#define DPTH  4              // cp.async ring slots (rows) per warp
#define ROWB  (CT * 4)       // 1536 bytes per staged row
#define LBLK  8              // loss blocks per batch
#define GRID2 180            // tail kernel blocks (= 2*BATCH*NPTS / 256)
#define TEMPF 100.0f
#define NEGV  -1e30f
#define TH_OFF 0.30f         // exp cutoff: e^(-30) ~ 1e-13 relative

// -------- scratch (static device globals; no allocation allowed) --------
__device__ float g_rowpart[BATCH * NCT * NPTS * 8];   // per (b,tile,row): m,s,px,py,pz,argcol
__device__ float g_colV[BATCH * NRT * NPTS];          // per (b,rowtile,col): col max value
__device__ float g_colVf[BATCH * NPTS];               // merged col max value
__device__ float g_p2[BATCH * NPTS * 4];              // points2 xyz + row max M
__device__ int   g_i21[BATCH * NPTS];                 // ind2to1
__device__ float4 g_part[BATCH * LBLK];               // loss partials (sm, sd, cnt)
__device__ unsigned g_c1;   // monotonic grid-barrier counter (never reset)
__device__ unsigned g_c2;   // monotonic finish ticket (never reset)

// -------- warp collectives --------
__device__ __forceinline__ unsigned f2ord(float f) {
    unsigned u = __float_as_uint(f);
    return (u & 0x80000000u) ? ~u : (u | 0x80000000u);
}
__device__ __forceinline__ float ord2f(unsigned u) {
    unsigned v = (u & 0x80000000u) ? (u & 0x7fffffffu) : ~u;
    return __uint_as_float(v);
}
__device__ __forceinline__ unsigned warp_max_u32(unsigned v) {
    unsigned r;
    asm volatile("redux.sync.max.u32 %0, %1, 0xffffffff;" : "=r"(r) : "r"(v));
    return r;
}
__device__ __forceinline__ unsigned warp_min_u32(unsigned v) {
    unsigned r;
    asm volatile("redux.sync.min.u32 %0, %1, 0xffffffff;" : "=r"(r) : "r"(v));
    return r;
}

// -------- cp.async helpers --------
__device__ __forceinline__ void cp16(uint32_t sdst, const void* gsrc) {
    asm volatile("cp.async.cg.shared.global [%0], [%1], 16;" :: "r"(sdst), "l"(gsrc));
}
__device__ __forceinline__ void cp_commit() {
    asm volatile("cp.async.commit_group;" ::: "memory");
}
template<int N> __device__ __forceinline__ void cp_wait() {
    asm volatile("cp.async.wait_group %0;" :: "n"(N) : "memory");
}
__device__ __forceinline__ void stage_row(uint32_t sdst, const float* grow, int lane) {
#pragma unroll
    for (int k = 0; k < GRP; k++)
        cp16(sdst + k * 512, (const void*)(grow + k * 128 + lane * 4));
    cp_commit();
}

// ================= K1: streaming pass, 2 rows per iteration (R11 verbatim) ==
extern __shared__ char dynsmem[];

__global__ void __launch_bounds__(TPB, 4) k_main(const float* __restrict__ match,
                                                 const float* __restrict__ tgt,
                                                 const int*   __restrict__ pmask)
{
    const int b    = blockIdx.z;
    const int tile = blockIdx.x;
    const int rt   = blockIdx.y;
    const int warp = threadIdx.x >> 5;
    const int lane = threadIdx.x & 31;
    const int col0 = tile * CT;
    const int row0 = rt * RT;

    const int* m1p = pmask + (size_t)(2 * b) * NPTS;
    const int* m2p = pmask + (size_t)(2 * b + 1) * NPTS;

    const uint32_t sbase = (uint32_t)__cvta_generic_to_shared(dynsmem);
    const uint32_t mybuf = sbase + (uint32_t)(warp * DPTH) * ROWB + lane * 16;

    unsigned m2b = 0;
    float cbv[EPL];
#pragma unroll
    for (int k = 0; k < GRP; k++) {
        int4 mm = *(const int4*)(m2p + col0 + k * 128 + lane * 4);
        m2b |= (mm.x ? 1u : 0u) << (4*k+0);
        m2b |= (mm.y ? 1u : 0u) << (4*k+1);
        m2b |= (mm.z ? 1u : 0u) << (4*k+2);
        m2b |= (mm.w ? 1u : 0u) << (4*k+3);
    }
#pragma unroll
    for (int e = 0; e < EPL; e++) cbv[e] = -INFINITY;

    const float* tgx = tgt + (size_t)(b * 3 + 0) * NPTS;
    const float* tgy = tgt + (size_t)(b * 3 + 1) * NPTS;
    const float* tgz = tgt + (size_t)(b * 3 + 2) * NPTS;

    const int rbeg = row0 + warp * RPW;
    bool vb = (lane < RPW) ? (m1p[rbeg + lane] != 0) : false;
    const unsigned mbits = __ballot_sync(0xffffffffu, vb);
    const int nval = __popc(mbits);

    const float* mbase = match + ((size_t)b * NPTS) * NPTS + col0;

    unsigned ccur = mbits;   // consume cursor
    unsigned scur = mbits;   // stage cursor (DPTH ahead)

#pragma unroll
    for (int i = 0; i < DPTH; i++) {
        if (scur) {
            int p = __ffs(scur) - 1; scur &= scur - 1;
            stage_row(mybuf + i * ROWB, mbase + (size_t)(rbeg + p) * NPTS, lane);
        } else {
            cp_commit();
        }
    }

    const int npair = (nval + 1) >> 1;
    for (int t = 0; t < npair; t++) {
        cp_wait<2>();                       // rows 2t, 2t+1 resident
        const int i0 = 2 * t;
        const bool hasB = (2 * t + 1 < nval);
        const int i1 = hasB ? 2 * t + 1 : i0;   // odd tail: dup (idempotent)
        int p0 = __ffs(ccur) - 1; ccur &= ccur - 1;
        int p1 = p0;
        if (hasB) { p1 = __ffs(ccur) - 1; ccur &= ccur - 1; }
        const int rA = rbeg + p0;
        const int rB = rbeg + p1;
        const char* bufA = dynsmem + (size_t)(warp * DPTH + (i0 & 3)) * ROWB + lane * 16;
        const char* bufB = dynsmem + (size_t)(warp * DPTH + (i1 & 3)) * ROWB + lane * 16;

        float gmA[GRP], gmB[GRP];
#pragma unroll
        for (int k = 0; k < GRP; k++) {
            float4 ta = *(const float4*)(bufA + k * 512);
            float4 tb = *(const float4*)(bufB + k * 512);
            const int e = 4 * k;
            cbv[e+0] = fmaxf(cbv[e+0], fmaxf(ta.x, tb.x));
            cbv[e+1] = fmaxf(cbv[e+1], fmaxf(ta.y, tb.y));
            cbv[e+2] = fmaxf(cbv[e+2], fmaxf(ta.z, tb.z));
            cbv[e+3] = fmaxf(cbv[e+3], fmaxf(ta.w, tb.w));
            float ga = -INFINITY, gb = -INFINITY;
            if (m2b & (1u << (e+0))) { ga = fmaxf(ga, ta.x); gb = fmaxf(gb, tb.x); }
            if (m2b & (1u << (e+1))) { ga = fmaxf(ga, ta.y); gb = fmaxf(gb, tb.y); }
            if (m2b & (1u << (e+2))) { ga = fmaxf(ga, ta.z); gb = fmaxf(gb, tb.z); }
            if (m2b & (1u << (e+3))) { ga = fmaxf(ga, ta.w); gb = fmaxf(gb, tb.w); }
            gmA[k] = ga; gmB[k] = gb;
        }
        const float lmA = fmaxf(fmaxf(gmA[0], gmA[1]), gmA[2]);
        const float lmB = fmaxf(fmaxf(gmB[0], gmB[1]), gmB[2]);
        const float wmA = ord2f(warp_max_u32(f2ord(lmA)));
        const float wmB = ord2f(warp_max_u32(f2ord(lmB)));
        const float thA = wmA - TH_OFF;
        const float thB = wmB - TH_OFF;

        float sA = 0.f, pxA = 0.f, pyA = 0.f, pzA = 0.f;
        float sB = 0.f, pxB = 0.f, pyB = 0.f, pzB = 0.f;
        unsigned bcA = 0x7fffffffu, bcB = 0x7fffffffu;
        if (lmA > thA) {
#pragma unroll
            for (int k = 0; k < GRP; k++) {
                if (gmA[k] > thA) {
                    float4 t4 = *(const float4*)(bufA + k * 512);
                    const float vv[4] = { t4.x, t4.y, t4.z, t4.w };
#pragma unroll
                    for (int j = 0; j < 4; j++) {
                        float vmv = (m2b & (1u << (4*k + j))) ? vv[j] : NEGV;
                        if (vmv > thA) {
                            float w = __expf((vmv - wmA) * TEMPF);
                            int c = col0 + k * 128 + lane * 4 + j;
                            sA  += w;
                            pxA += w * tgx[c];
                            pyA += w * tgy[c];
                            pzA += w * tgz[c];
                            if (vmv == wmA) bcA = min(bcA, (unsigned)c);
                        }
                    }
                }
            }
        }
        if (lmB > thB) {
#pragma unroll
            for (int k = 0; k < GRP; k++) {
                if (gmB[k] > thB) {
                    float4 t4 = *(const float4*)(bufB + k * 512);
                    const float vv[4] = { t4.x, t4.y, t4.z, t4.w };
#pragma unroll
                    for (int j = 0; j < 4; j++) {
                        float vmv = (m2b & (1u << (4*k + j))) ? vv[j] : NEGV;
                        if (vmv > thB) {
                            float w = __expf((vmv - wmB) * TEMPF);
                            int c = col0 + k * 128 + lane * 4 + j;
                            sB  += w;
                            pxB += w * tgx[c];
                            pyB += w * tgy[c];
                            pzB += w * tgz[c];
                            if (vmv == wmB) bcB = min(bcB, (unsigned)c);
                        }
                    }
                }
            }
        }

        {
            const unsigned bal = __ballot_sync(0xffffffffu, lmA > thA);
            float* out = g_rowpart + ((size_t)(b * NCT + tile) * NPTS + rA) * 8;
            if (__popc(bal) == 1) {
                if (lane == __ffs(bal) - 1) {
                    *(float4*)(out)     = make_float4(wmA, sA, pxA, pyA);
                    *(float4*)(out + 4) = make_float4(pzA, __int_as_float((int)bcA), 0.f, 0.f);
                }
            } else {
#pragma unroll
                for (int o = 16; o; o >>= 1) {
                    sA  += __shfl_xor_sync(0xffffffffu, sA,  o);
                    pxA += __shfl_xor_sync(0xffffffffu, pxA, o);
                    pyA += __shfl_xor_sync(0xffffffffu, pyA, o);
                    pzA += __shfl_xor_sync(0xffffffffu, pzA, o);
                }
                bcA = warp_min_u32(bcA);
                if (lane == 0) {
                    *(float4*)(out)     = make_float4(wmA, sA, pxA, pyA);
                    *(float4*)(out + 4) = make_float4(pzA, __int_as_float((int)bcA), 0.f, 0.f);
                }
            }
        }
        {
            const unsigned bal = __ballot_sync(0xffffffffu, lmB > thB);
            float* out = g_rowpart + ((size_t)(b * NCT + tile) * NPTS + rB) * 8;
            if (__popc(bal) == 1) {
                if (lane == __ffs(bal) - 1) {
                    *(float4*)(out)     = make_float4(wmB, sB, pxB, pyB);
                    *(float4*)(out + 4) = make_float4(pzB, __int_as_float((int)bcB), 0.f, 0.f);
                }
            } else {
#pragma unroll
                for (int o = 16; o; o >>= 1) {
                    sB  += __shfl_xor_sync(0xffffffffu, sB,  o);
                    pxB += __shfl_xor_sync(0xffffffffu, pxB, o);
                    pyB += __shfl_xor_sync(0xffffffffu, pyB, o);
                    pzB += __shfl_xor_sync(0xffffffffu, pzB, o);
                }
                bcB = warp_min_u32(bcB);
                if (lane == 0) {
                    *(float4*)(out)     = make_float4(wmB, sB, pxB, pyB);
                    *(float4*)(out + 4) = make_float4(pzB, __int_as_float((int)bcB), 0.f, 0.f);
                }
            }
        }

#pragma unroll
        for (int d = 0; d < 2; d++) {
            int j = 2 * t + DPTH + d;
            if (j < nval && scur) {
                int p = __ffs(scur) - 1; scur &= scur - 1;
                stage_row(mybuf + (j & 3) * ROWB, mbase + (size_t)(rbeg + p) * NPTS, lane);
            } else {
                cp_commit();
            }
        }
    }
    cp_wait<0>();
    __syncthreads();

    // block-level column-max merge (values only)
    float* sv = (float*)dynsmem;                       // [WARPS][CT]
#pragma unroll
    for (int e = 0; e < EPL; e++) {
        int cl = (e >> 2) * 128 + lane * 4 + (e & 3);
        sv[warp * CT + cl] = cbv[e];
    }
    __syncthreads();
    for (int c = threadIdx.x; c < CT; c += TPB) {
        float bv = -INFINITY;
#pragma unroll
        for (int w = 0; w < WARPS; w++) bv = fmaxf(bv, sv[w * CT + c]);
        g_colV[(size_t)(b * NRT + rt) * NPTS + col0 + c] = bv;
    }
}

// ====== K2: fused merge + grid barrier + loss (monotonic tickets) ===========
__global__ void __launch_bounds__(256) k_tail(const float* __restrict__ src,
                                              const float* __restrict__ wts,
                                              const float* __restrict__ Tiv,
                                              const int*   __restrict__ pmask,
                                              float* __restrict__ out)
{
    const int gid = blockIdx.x * 256 + threadIdx.x;
    const int total = BATCH * NPTS;

    // ---- phase 1: merge row tiles + column tiles ----
    if (gid < total) {
        const int b = gid / NPTS, r = gid - b * NPTS;
        if (pmask[(size_t)(2 * b) * NPTS + r]) {
            float M = -INFINITY; int argc = 0;
            float4 A[NCT], Bv[NCT];
#pragma unroll
            for (int t = 0; t < NCT; t++) {
                const float* base = g_rowpart + ((size_t)(b * NCT + t) * NPTS + r) * 8;
                A[t]  = *(const float4*)(base);
                Bv[t] = *(const float4*)(base + 4);
            }
#pragma unroll
            for (int t = 0; t < NCT; t++)
                if (A[t].x > M) { M = A[t].x; argc = __float_as_int(Bv[t].y); }
            float S = 0.f, Px = 0.f, Py = 0.f, Pz = 0.f;
#pragma unroll
            for (int t = 0; t < NCT; t++) {
                float w = __expf((A[t].x - M) * TEMPF);
                S  += A[t].y * w;
                Px += A[t].z * w;
                Py += A[t].w * w;
                Pz += Bv[t].x * w;
            }
            float inv = 1.f / S;
            *(float4*)(g_p2 + (size_t)gid * 4) = make_float4(Px * inv, Py * inv, Pz * inv, M);
            g_i21[gid] = argc;
        }
    } else if (gid < 2 * total) {
        const int g2 = gid - total;
        const int b = g2 / NPTS, c = g2 - b * NPTS;
        float bv = -INFINITY;
#pragma unroll
        for (int t = 0; t < NRT; t++)
            bv = fmaxf(bv, g_colV[(size_t)(b * NRT + t) * NPTS + c]);
        g_colVf[g2] = bv;
    }

    // ---- grid barrier: monotonic ticket (no reset => no race, replay-safe) --
    __threadfence();
    __syncthreads();
    if (threadIdx.x == 0) {
        unsigned old = atomicAdd(&g_c1, 1u);
        unsigned target = old - (old % GRID2) + GRID2;   // this replay's goal
        volatile unsigned* vc = &g_c1;
        while (*vc < target) { }
    }
    __syncthreads();
    __threadfence();

    // blocks >= 32 are done
    if (blockIdx.x >= BATCH * LBLK) return;

    // ---- phase 2: loss partials (32 blocks) ----
    const int b   = blockIdx.x / LBLK;
    const int blk = blockIdx.x % LBLK;
    const int CH  = NPTS / LBLK;                 // 720 points per block

    __shared__ float T21[12];
    if (threadIdx.x == 0) {
        const float* Ts = Tiv + (size_t)(2 * b) * 16;
        const float* Tt = Tiv + (size_t)(2 * b + 1) * 16;
        float A[3][4];
        for (int i = 0; i < 3; i++) {
            for (int k = 0; k < 3; k++) A[i][k] = Tt[k * 4 + i];
            A[i][3] = -(Tt[0*4+i]*Tt[3] + Tt[1*4+i]*Tt[7] + Tt[2*4+i]*Tt[11]);
        }
        for (int i = 0; i < 3; i++)
            for (int j = 0; j < 4; j++)
                T21[i*4+j] = A[i][0]*Ts[j] + A[i][1]*Ts[4+j]
                           + A[i][2]*Ts[8+j] + A[i][3]*Ts[12+j];
    }
    __syncthreads();

    const float* sx = src + (size_t)(b * 3 + 0) * NPTS;
    const float* sy = src + (size_t)(b * 3 + 1) * NPTS;
    const float* sz = src + (size_t)(b * 3 + 2) * NPTS;
    const float* w0 = wts + (size_t)(b * 6 + 0) * NPTS;
    const float* w1 = wts + (size_t)(b * 6 + 1) * NPTS;
    const float* w2 = wts + (size_t)(b * 6 + 2) * NPTS;
    const float* w3 = wts + (size_t)(b * 6 + 3) * NPTS;
    const float* w4 = wts + (size_t)(b * 6 + 4) * NPTS;
    const float* w5 = wts + (size_t)(b * 6 + 5) * NPTS;
    const int*   m1  = pmask + (size_t)(2 * b) * NPTS;
    const int*   i21 = g_i21 + b * NPTS;
    const float* cvf = g_colVf + b * NPTS;

    float sm = 0.f, sd = 0.f, cnt = 0.f;
    const int i0 = blk * CH;
    for (int i = i0 + threadIdx.x; i < i0 + CH; i += 256) {
        if (!m1[i]) continue;
        float4 pp = *(const float4*)(g_p2 + (size_t)(b * NPTS + i) * 4);
        int j = i21[i];
        if (pp.w != cvf[j]) continue;   // consist: row max == its column's max
        float p0 = sx[i], p1 = sy[i], p2v = sz[i];
        float q0 = T21[0]*p0 + T21[1]*p1 + T21[2] *p2v + T21[3];
        float q1 = T21[4]*p0 + T21[5]*p1 + T21[6] *p2v + T21[7];
        float q2 = T21[8]*p0 + T21[9]*p1 + T21[10]*p2v + T21[11];
        float e0 = q0 - pp.x, e1 = q1 - pp.y, e2 = q2 - pp.z;
        float aa = w0[i], bb = w1[i], cc = w2[i];
        float d0 = w3[i], d1 = w4[i], d2 = w5[i];
        float u0 = e0 + aa * e1 + bb * e2;
        float u1 = e1 + cc * e2;
        float u2 = e2;
        float mah = __expf(d0)*u0*u0 + __expf(d1)*u1*u1 + __expf(d2)*u2*u2;
        if (mah < 10000.0f) { sm += mah; sd += d0 + d1 + d2; cnt += 1.f; }
    }
#pragma unroll
    for (int o = 16; o; o >>= 1) {
        sm  += __shfl_xor_sync(0xffffffffu, sm,  o);
        sd  += __shfl_xor_sync(0xffffffffu, sd,  o);
        cnt += __shfl_xor_sync(0xffffffffu, cnt, o);
    }
    __shared__ float rs[8], rd[8], rc[8];
    if ((threadIdx.x & 31) == 0) {
        rs[threadIdx.x >> 5] = sm;
        rd[threadIdx.x >> 5] = sd;
        rc[threadIdx.x >> 5] = cnt;
    }
    __syncthreads();
    if (threadIdx.x == 0) {
        float S = 0.f, D = 0.f, C = 0.f;
        for (int w = 0; w < 8; w++) { S += rs[w]; D += rd[w]; C += rc[w]; }
        g_part[b * LBLK + blk] = make_float4(S, D, C, 0.f);
        __threadfence();
        // monotonic finish ticket: last of this replay's 32 sums the output
        unsigned old2 = atomicAdd(&g_c2, 1u);
        if ((old2 % (BATCH * LBLK)) == (BATCH * LBLK - 1)) {
            __threadfence();
            float acc = 0.f;
            for (int bb = 0; bb < BATCH; bb++) {
                float S2 = 0.f, D2 = 0.f, C2 = 0.f;
                for (int k = 0; k < LBLK; k++) {
                    float4 p = g_part[bb * LBLK + k];
                    S2 += p.x; D2 += p.y; C2 += p.z;
                }
                acc += (S2 - D2) / fmaxf(C2, 1.f);
            }
            out[0] = acc;
        }
    }
}

// ================= launch ====================================================
extern "C" void kernel_launch(void* const* d_in, const int* in_sizes, int n_in,
                              void* d_out, int out_size)
{
    const float* src   = (const float*)d_in[0];   // (4,3,5760)
    const float* tgt   = (const float*)d_in[1];   // (4,3,5760)
    const float* wts   = (const float*)d_in[2];   // (4,6,5760)
    const float* match = (const float*)d_in[3];   // (4,5760,5760)
    const float* Tiv   = (const float*)d_in[4];   // (8,4,4)
    const int*   pmask = (const int*)d_in[5];     // (8,5760)

    const int dynbytes = WARPS * DPTH * ROWB;     // 48 KB ring per block
    static int configured = 0;
    if (!configured) {
        cudaFuncSetAttribute(k_main, cudaFuncAttributeMaxDynamicSharedMemorySize, dynbytes);
        configured = 1;
    }

    dim3 g1(NCT, NRT, BATCH);                     // 15 x 24 x 4 = 1440 blocks
    k_main<<<g1, TPB, dynbytes>>>(match, tgt, pmask);

    k_tail<<<GRID2, 256>>>(src, wts, Tiv, pmask, (float*)d_out);
}